// round 3
// baseline (speedup 1.0000x reference)
#include <cuda_runtime.h>

#define DD 32          // embed dim
#define GI_W 96        // 3*DD gate width
#define NSYM 64        // distinct path symbol values

// Precomputed tables (device globals: no dynamic allocation allowed)
__device__ float g_GI_ent[NSYM * GI_W];   // W_ih @ all_emb[e] + b_ih   (even positions)
__device__ float g_GI_rel[NSYM * GI_W];   // W_ih @ edge_emb[r] + b_ih  (odd positions)
__device__ float g_H2[NSYM * NSYM * DD];  // GRU state after 2 steps, keyed (p0, p1)

// ---------------------------------------------------------------------------
// TF32 emulation: the JAX reference runs its matmuls (gi einsum, h@w_hh.T,
// h@w_lin.T) as TF32 tensor-core GEMMs. Round GEMM operands to TF32;
// tf32*tf32 products are exact in fp32, accumulate fp32.
// ---------------------------------------------------------------------------
__device__ __forceinline__ float tf32r(float x) {
    float r;
    asm("cvt.rna.tf32.f32 %0, %1;" : "=f"(r) : "f"(x));
    return r;
}

__device__ __forceinline__ float sig_acc(float x) {
    float e = __expf(-x);
    return __fdiv_rn(1.0f, 1.0f + e);
}
__device__ __forceinline__ float tanh_acc(float x) {
    float a = fabsf(x);
    float em = expm1f(-2.0f * a);            // e^{-2a} - 1, in [-1, 0]
    float t = __fdiv_rn(-em, 2.0f + em);     // tanh(a), no cancellation
    return copysignf(t, x);
}

// ---------------------------------------------------------------------------
// One GRU step: h <- GRU(h, x) with gi = W_ih x + b_ih precomputed.
// ws4 holds TF32-rounded w_hh rows (rounded once at smem load).
// h is rounded to TF32 once per step for the dots; the state update uses
// the full-precision h (matches reference: rounding lives inside the GEMM).
// Chunk order r -> n -> z so z never needs a 32-wide register array.
// ---------------------------------------------------------------------------
__device__ __forceinline__ void gru_step(float h[DD], const float* __restrict__ gi,
                                         const float4* __restrict__ ws4,
                                         const float* __restrict__ bs) {
    float hr[DD];                 // TF32-rounded copy of h (GEMM operand)
    #pragma unroll
    for (int k = 0; k < DD; k++) hr[k] = tf32r(h[k]);

    float rn[DD];
    float4 giv[8];
    const float4* gi4 = (const float4*)gi;

    // --- r chunk (rows 0..31) ---
    #pragma unroll
    for (int q = 0; q < 8; q++) giv[q] = __ldg(gi4 + q);
    #pragma unroll
    for (int j = 0; j < DD; j++) {
        float a0 = 0.0f, a1 = 0.0f;
        #pragma unroll
        for (int q = 0; q < 4; q++) {
            float4 w0 = ws4[j * 8 + q];
            float4 w1 = ws4[j * 8 + 4 + q];
            a0 = fmaf(w0.x, hr[4 * q + 0], a0);
            a0 = fmaf(w0.y, hr[4 * q + 1], a0);
            a0 = fmaf(w0.z, hr[4 * q + 2], a0);
            a0 = fmaf(w0.w, hr[4 * q + 3], a0);
            a1 = fmaf(w1.x, hr[16 + 4 * q + 0], a1);
            a1 = fmaf(w1.y, hr[16 + 4 * q + 1], a1);
            a1 = fmaf(w1.z, hr[16 + 4 * q + 2], a1);
            a1 = fmaf(w1.w, hr[16 + 4 * q + 3], a1);
        }
        float gh = (a0 + a1) + bs[j];
        rn[j] = sig_acc(((const float*)giv)[j] + gh);
    }

    // --- n chunk (rows 64..95): n = tanh(gi_n + r * gh_n) ---
    #pragma unroll
    for (int q = 0; q < 8; q++) giv[q] = __ldg(gi4 + 16 + q);
    #pragma unroll
    for (int j = 0; j < DD; j++) {
        float a0 = 0.0f, a1 = 0.0f;
        #pragma unroll
        for (int q = 0; q < 4; q++) {
            float4 w0 = ws4[(64 + j) * 8 + q];
            float4 w1 = ws4[(64 + j) * 8 + 4 + q];
            a0 = fmaf(w0.x, hr[4 * q + 0], a0);
            a0 = fmaf(w0.y, hr[4 * q + 1], a0);
            a0 = fmaf(w0.z, hr[4 * q + 2], a0);
            a0 = fmaf(w0.w, hr[4 * q + 3], a0);
            a1 = fmaf(w1.x, hr[16 + 4 * q + 0], a1);
            a1 = fmaf(w1.y, hr[16 + 4 * q + 1], a1);
            a1 = fmaf(w1.z, hr[16 + 4 * q + 2], a1);
            a1 = fmaf(w1.w, hr[16 + 4 * q + 3], a1);
        }
        float gh = (a0 + a1) + bs[64 + j];
        rn[j] = tanh_acc(fmaf(rn[j], gh, ((const float*)giv)[j]));
    }

    // --- z chunk (rows 32..63) + state update: h = (1-z)*n + z*h ---
    #pragma unroll
    for (int q = 0; q < 8; q++) giv[q] = __ldg(gi4 + 8 + q);
    #pragma unroll
    for (int j = 0; j < DD; j++) {
        float a0 = 0.0f, a1 = 0.0f;
        #pragma unroll
        for (int q = 0; q < 4; q++) {
            float4 w0 = ws4[(32 + j) * 8 + q];
            float4 w1 = ws4[(32 + j) * 8 + 4 + q];
            a0 = fmaf(w0.x, hr[4 * q + 0], a0);
            a0 = fmaf(w0.y, hr[4 * q + 1], a0);
            a0 = fmaf(w0.z, hr[4 * q + 2], a0);
            a0 = fmaf(w0.w, hr[4 * q + 3], a0);
            a1 = fmaf(w1.x, hr[16 + 4 * q + 0], a1);
            a1 = fmaf(w1.y, hr[16 + 4 * q + 1], a1);
            a1 = fmaf(w1.z, hr[16 + 4 * q + 2], a1);
            a1 = fmaf(w1.w, hr[16 + 4 * q + 3], a1);
        }
        float gh = (a0 + a1) + bs[32 + j];
        float z = sig_acc(((const float*)giv)[j] + gh);
        h[j] = fmaf(z, h[j], (1.0f - z) * rn[j]);
    }
}

// ---------------------------------------------------------------------------
// K0: zero the (poisoned) output
// ---------------------------------------------------------------------------
__global__ void k_zero(float* out, int n) {
    int i = threadIdx.x;
    if (i < n) out[i] = 0.0f;
}

// ---------------------------------------------------------------------------
// K1: GI tables — TF32 products (matching the reference einsum), fp64 sum.
// grid = 128 rows (64 entity + 64 relation), block = 96 (gate j)
// ---------------------------------------------------------------------------
__global__ void k_gi(const float* __restrict__ all_emb,
                     const float* __restrict__ edge_emb,
                     const float* __restrict__ w_ih,
                     const float* __restrict__ b_ih) {
    int row = blockIdx.x;      // 0..127
    int j = threadIdx.x;       // 0..95
    const float* x = (row < NSYM) ? (all_emb + row * DD)
                                  : (edge_emb + (row - NSYM) * DD);
    const float* w = w_ih + j * DD;
    double acc = 0.0;
    #pragma unroll
    for (int k = 0; k < DD; k++) {
        float wt = tf32r(__ldg(w + k));
        float xt = tf32r(__ldg(x + k));
        acc += (double)wt * (double)xt;     // tf32*tf32 exact
    }
    acc += (double)__ldg(b_ih + j);
    float* dst = (row < NSYM) ? (g_GI_ent + row * GI_W)
                              : (g_GI_rel + (row - NSYM) * GI_W);
    dst[j] = (float)acc;
}

// ---------------------------------------------------------------------------
// K2: H2 table. One thread per (p0, p1) key: steps 1 and 2 of the GRU.
// ---------------------------------------------------------------------------
__global__ void __launch_bounds__(128) k_h2(const float* __restrict__ w_hh,
                                            const float* __restrict__ b_hh) {
    __shared__ float4 ws4[GI_W * 8];
    __shared__ float bs[GI_W];
    int tid = threadIdx.x;
    for (int i = tid; i < GI_W * 8; i += 128) {
        float4 v = ((const float4*)w_hh)[i];
        ws4[i] = make_float4(tf32r(v.x), tf32r(v.y), tf32r(v.z), tf32r(v.w));
    }
    if (tid < GI_W) bs[tid] = b_hh[tid];
    __syncthreads();

    int key = blockIdx.x * 128 + tid;        // 0..4095
    int e0 = key >> 6, r1 = key & 63;

    // step 1: h0 = 0 => gh = b_hh exactly (TF32 GEMM of zeros is zero)
    const float* gi = g_GI_ent + e0 * GI_W;
    float h[DD];
    #pragma unroll
    for (int j = 0; j < DD; j++) {
        float r = sig_acc(__ldg(gi + j) + bs[j]);
        float z = sig_acc(__ldg(gi + 32 + j) + bs[32 + j]);
        float n = tanh_acc(fmaf(r, bs[64 + j], __ldg(gi + 64 + j)));
        h[j] = (1.0f - z) * n;               // + z*0
    }
    // step 2
    gru_step(h, g_GI_rel + r1 * GI_W, ws4, bs);

    float4* dst = (float4*)(g_H2 + key * DD);
    #pragma unroll
    for (int q = 0; q < 8; q++)
        dst[q] = make_float4(h[4 * q], h[4 * q + 1], h[4 * q + 2], h[4 * q + 3]);
}

// ---------------------------------------------------------------------------
// K3: main per-path kernel. One thread per path: load h2, 3 GRU steps,
//     linear head, atomic segment sum.
// ---------------------------------------------------------------------------
__global__ void __launch_bounds__(128) k_main(
        const int* __restrict__ path, const int* __restrict__ path_idx,
        const float* __restrict__ w_hh, const float* __restrict__ b_hh,
        const float* __restrict__ w_lin, const float* __restrict__ b_lin,
        float* __restrict__ out, int n_paths) {
    __shared__ float4 ws4[GI_W * 8];
    __shared__ float bs[GI_W];
    __shared__ float wl[DD];
    __shared__ float bl;
    int tid = threadIdx.x;
    for (int i = tid; i < GI_W * 8; i += 128) {
        float4 v = ((const float4*)w_hh)[i];
        ws4[i] = make_float4(tf32r(v.x), tf32r(v.y), tf32r(v.z), tf32r(v.w));
    }
    if (tid < GI_W) bs[tid] = b_hh[tid];
    if (tid < DD) wl[tid] = tf32r(w_lin[tid]);
    if (tid == 0) bl = b_lin[0];
    __syncthreads();

    int p = blockIdx.x * 128 + tid;
    if (p >= n_paths) return;

    int b0 = __ldg(path + p * 5 + 0);
    int b1 = __ldg(path + p * 5 + 1);
    int b2 = __ldg(path + p * 5 + 2);
    int b3 = __ldg(path + p * 5 + 3);
    int b4 = __ldg(path + p * 5 + 4);

    float h[DD];
    const float4* h2 = (const float4*)(g_H2 + (b0 * NSYM + b1) * DD);
    #pragma unroll
    for (int q = 0; q < 8; q++) {
        float4 v = __ldg(h2 + q);
        h[4 * q + 0] = v.x; h[4 * q + 1] = v.y;
        h[4 * q + 2] = v.z; h[4 * q + 3] = v.w;
    }

    const float* g2 = g_GI_ent + b2 * GI_W;
    const float* g3 = g_GI_rel + b3 * GI_W;
    const float* g4 = g_GI_ent + b4 * GI_W;
    #pragma unroll 1
    for (int t = 0; t < 3; t++) {
        const float* gi = (t == 0) ? g2 : (t == 1) ? g3 : g4;
        gru_step(h, gi, ws4, bs);
    }

    // per_path = h . w_lin + b_lin  (TF32 operands, fp32 acc, bias last)
    float s0 = 0.0f, s1 = 0.0f;
    #pragma unroll
    for (int j = 0; j < 16; j++) {
        s0 = fmaf(tf32r(h[j]), wl[j], s0);
        s1 = fmaf(tf32r(h[16 + j]), wl[16 + j], s1);
    }
    float s = (s0 + s1) + bl;

    atomicAdd(out + __ldg(path_idx + p), s);
}

// ---------------------------------------------------------------------------
extern "C" void kernel_launch(void* const* d_in, const int* in_sizes, int n_in,
                              void* d_out, int out_size) {
    // inputs: 0 users, 1 path, 2 path_idx, 3 all_emb, 4 edge_emb, 5 virtual_emb,
    //         6 w_ih, 7 w_hh, 8 b_ih, 9 b_hh, 10 w_lin, 11 b_lin
    const int*   path     = (const int*)d_in[1];
    const int*   path_idx = (const int*)d_in[2];
    const float* all_emb  = (const float*)d_in[3];
    const float* edge_emb = (const float*)d_in[4];
    const float* w_ih     = (const float*)d_in[6];
    const float* w_hh     = (const float*)d_in[7];
    const float* b_ih     = (const float*)d_in[8];
    const float* b_hh     = (const float*)d_in[9];
    const float* w_lin    = (const float*)d_in[10];
    const float* b_lin    = (const float*)d_in[11];
    float* out = (float*)d_out;
    int n_paths = in_sizes[2];

    k_zero<<<1, 1024>>>(out, out_size);
    k_gi<<<128, 96>>>(all_emb, edge_emb, w_ih, b_ih);
    k_h2<<<32, 128>>>(w_hh, b_hh);
    int grid = (n_paths + 127) / 128;
    k_main<<<grid, 128>>>(path, path_idx, w_hh, b_hh, w_lin, b_lin, out, n_paths);
}

// round 4
// speedup vs baseline: 1.2597x; 1.2597x over previous
#include <cuda_runtime.h>

#define DD 32          // embed dim
#define GI_W 96        // 3*DD gate width
#define NSYM 64        // distinct path symbol values

typedef unsigned long long u64;

// Precomputed tables (device globals: no dynamic allocation allowed)
__device__ float g_GI_ent[NSYM * GI_W];   // W_ih @ all_emb[e] + b_ih   (even positions)
__device__ float g_GI_rel[NSYM * GI_W];   // W_ih @ edge_emb[r] + b_ih  (odd positions)
__device__ float g_H2[NSYM * NSYM * DD];  // GRU state after 2 steps, keyed (p0, p1)

// ---------------------------------------------------------------------------
// TF32 emulation (the reference's matmuls are TF32 tensor-core GEMMs):
// round GEMM operands to TF32, accumulate fp32. tf32*tf32 is exact in fp32.
// ---------------------------------------------------------------------------
__device__ __forceinline__ float tf32r(float x) {
    float r;
    asm("cvt.rna.tf32.f32 %0, %1;" : "=f"(r) : "f"(x));
    return r;
}

// Packed f32x2 helpers (sm_100+; FFMA2 in SASS, only reachable via PTX)
__device__ __forceinline__ u64 pack2(float lo, float hi) {
    u64 r; asm("mov.b64 %0, {%1, %2};" : "=l"(r) : "f"(lo), "f"(hi)); return r;
}
__device__ __forceinline__ void unpack2(u64 v, float& lo, float& hi) {
    asm("mov.b64 {%0, %1}, %2;" : "=f"(lo), "=f"(hi) : "l"(v));
}
__device__ __forceinline__ u64 fma2(u64 a, u64 b, u64 c) {
    u64 d; asm("fma.rn.f32x2 %0, %1, %2, %3;" : "=l"(d) : "l"(a), "l"(b), "l"(c));
    return d;
}
__device__ __forceinline__ u64 mul2(u64 a, u64 b) {
    u64 d; asm("mul.rn.f32x2 %0, %1, %2;" : "=l"(d) : "l"(a), "l"(b));
    return d;
}

// Fast activations — proven in round 1 to contribute <=4e-8 to final rel_err
// (vs the 4.3e-4 TF32 floor).
__device__ __forceinline__ float sigf(float x) {
    return __fdividef(1.0f, 1.0f + __expf(-x));
}
__device__ __forceinline__ float tanh_fast(float x) {
    return fmaf(2.0f, sigf(2.0f * x), -1.0f);
}

// 32-wide dot of one TF32-rounded w_hh row (8 ulonglong2 in smem, broadcast
// LDS.128) against packed TF32-rounded h. Dual packed accumulators.
__device__ __forceinline__ float dot32(const ulonglong2* __restrict__ wrow,
                                       const u64 hr[16]) {
    u64 a0 = 0ull, a1 = 0ull;   // packed {0.f, 0.f}
    #pragma unroll
    for (int q = 0; q < 8; q++) {
        ulonglong2 w = wrow[q];
        a0 = fma2(w.x, hr[2 * q + 0], a0);
        a1 = fma2(w.y, hr[2 * q + 1], a1);
    }
    float x0, x1, y0, y1;
    unpack2(a0, x0, x1);
    unpack2(a1, y0, y1);
    return (x0 + y0) + (x1 + y1);
}

// ---------------------------------------------------------------------------
// One GRU step on packed state hu[16] ({h0,h1},{h2,h3},...).
// ws: 96 rows x 8 ulonglong2 of TF32-rounded w_hh. bs: b_hh (fp32).
// Chunk order r -> n -> z; rn[16] holds r then n (packed).
// ---------------------------------------------------------------------------
__device__ __forceinline__ void gru_step(u64 hu[16], const float* __restrict__ gi,
                                         const ulonglong2* __restrict__ ws,
                                         const float* __restrict__ bs) {
    // TF32-round the GEMM operand copy of h (state itself stays full fp32)
    u64 hr[16];
    #pragma unroll
    for (int p = 0; p < 16; p++) {
        float lo, hi; unpack2(hu[p], lo, hi);
        hr[p] = pack2(tf32r(lo), tf32r(hi));
    }

    u64 rn[16];
    const float4* gi4 = (const float4*)gi;
    float4 giv;

    // --- r chunk (rows 0..31) ---
    #pragma unroll
    for (int jp = 0; jp < 16; jp++) {
        if ((jp & 1) == 0) giv = __ldg(gi4 + (jp >> 1));
        float g0 = (jp & 1) ? giv.z : giv.x;
        float g1 = (jp & 1) ? giv.w : giv.y;
        float d0 = dot32(ws + (2 * jp + 0) * 8, hr);
        float d1 = dot32(ws + (2 * jp + 1) * 8, hr);
        float r0 = sigf(g0 + (d0 + bs[2 * jp + 0]));
        float r1 = sigf(g1 + (d1 + bs[2 * jp + 1]));
        rn[jp] = pack2(r0, r1);
    }

    // --- n chunk (rows 64..95): n = tanh(gi_n + r * gh_n) ---
    #pragma unroll
    for (int jp = 0; jp < 16; jp++) {
        if ((jp & 1) == 0) giv = __ldg(gi4 + 16 + (jp >> 1));
        float g0 = (jp & 1) ? giv.z : giv.x;
        float g1 = (jp & 1) ? giv.w : giv.y;
        float d0 = dot32(ws + (64 + 2 * jp + 0) * 8, hr);
        float d1 = dot32(ws + (64 + 2 * jp + 1) * 8, hr);
        float r0, r1; unpack2(rn[jp], r0, r1);
        float n0 = tanh_fast(fmaf(r0, d0 + bs[64 + 2 * jp + 0], g0));
        float n1 = tanh_fast(fmaf(r1, d1 + bs[64 + 2 * jp + 1], g1));
        rn[jp] = pack2(n0, n1);
    }

    // --- z chunk (rows 32..63) + packed update: h = z*h + (1-z)*n ---
    #pragma unroll
    for (int jp = 0; jp < 16; jp++) {
        if ((jp & 1) == 0) giv = __ldg(gi4 + 8 + (jp >> 1));
        float g0 = (jp & 1) ? giv.z : giv.x;
        float g1 = (jp & 1) ? giv.w : giv.y;
        float d0 = dot32(ws + (32 + 2 * jp + 0) * 8, hr);
        float d1 = dot32(ws + (32 + 2 * jp + 1) * 8, hr);
        float z0 = sigf(g0 + (d0 + bs[32 + 2 * jp + 0]));
        float z1 = sigf(g1 + (d1 + bs[32 + 2 * jp + 1]));
        u64 zz  = pack2(z0, z1);
        u64 omz = pack2(1.0f - z0, 1.0f - z1);
        hu[jp] = fma2(zz, hu[jp], mul2(omz, rn[jp]));
    }
}

// Shared loader: w_hh -> TF32-rounded packed rows in smem
__device__ __forceinline__ void load_ws(ulonglong2* ws, const float* __restrict__ w_hh,
                                        int tid, int nthreads) {
    for (int i = tid; i < GI_W * 8; i += nthreads) {
        float4 v = ((const float4*)w_hh)[i];
        ulonglong2 e;
        e.x = pack2(tf32r(v.x), tf32r(v.y));
        e.y = pack2(tf32r(v.z), tf32r(v.w));
        ws[i] = e;
    }
}

// ---------------------------------------------------------------------------
// K0: zero the (poisoned) output
// ---------------------------------------------------------------------------
__global__ void k_zero(float* out, int n) {
    int i = threadIdx.x;
    if (i < n) out[i] = 0.0f;
}

// ---------------------------------------------------------------------------
// K1: GI tables — TF32 products (matching the reference einsum), fp64 sum.
// ---------------------------------------------------------------------------
__global__ void k_gi(const float* __restrict__ all_emb,
                     const float* __restrict__ edge_emb,
                     const float* __restrict__ w_ih,
                     const float* __restrict__ b_ih) {
    int row = blockIdx.x;      // 0..127
    int j = threadIdx.x;       // 0..95
    const float* x = (row < NSYM) ? (all_emb + row * DD)
                                  : (edge_emb + (row - NSYM) * DD);
    const float* w = w_ih + j * DD;
    double acc = 0.0;
    #pragma unroll
    for (int k = 0; k < DD; k++) {
        float wt = tf32r(__ldg(w + k));
        float xt = tf32r(__ldg(x + k));
        acc += (double)wt * (double)xt;     // tf32*tf32 exact
    }
    acc += (double)__ldg(b_ih + j);
    float* dst = (row < NSYM) ? (g_GI_ent + row * GI_W)
                              : (g_GI_rel + (row - NSYM) * GI_W);
    dst[j] = (float)acc;
}

// ---------------------------------------------------------------------------
// K2: H2 table. One thread per (p0, p1) key: steps 1 and 2 of the GRU.
// ---------------------------------------------------------------------------
__global__ void __launch_bounds__(128, 3) k_h2(const float* __restrict__ w_hh,
                                               const float* __restrict__ b_hh) {
    __shared__ ulonglong2 ws[GI_W * 8];
    __shared__ float bs[GI_W];
    int tid = threadIdx.x;
    load_ws(ws, w_hh, tid, 128);
    if (tid < GI_W) bs[tid] = b_hh[tid];
    __syncthreads();

    int key = blockIdx.x * 128 + tid;        // 0..4095
    int e0 = key >> 6, r1 = key & 63;

    // step 1: h0 = 0 => gh = b_hh exactly (TF32 GEMM of zeros is zero)
    const float* gi = g_GI_ent + e0 * GI_W;
    u64 hu[16];
    #pragma unroll
    for (int jp = 0; jp < 16; jp++) {
        float hv[2];
        #pragma unroll
        for (int t = 0; t < 2; t++) {
            int j = 2 * jp + t;
            float r = sigf(__ldg(gi + j) + bs[j]);
            float z = sigf(__ldg(gi + 32 + j) + bs[32 + j]);
            float n = tanh_fast(fmaf(r, bs[64 + j], __ldg(gi + 64 + j)));
            hv[t] = (1.0f - z) * n;          // + z*0
        }
        hu[jp] = pack2(hv[0], hv[1]);
    }
    // step 2
    gru_step(hu, g_GI_rel + r1 * GI_W, ws, bs);

    u64* dst = (u64*)(g_H2 + key * DD);
    #pragma unroll
    for (int p = 0; p < 16; p++) dst[p] = hu[p];
}

// ---------------------------------------------------------------------------
// K3: main per-path kernel. One thread per path: load h2, 3 GRU steps,
//     linear head, atomic segment sum.
// ---------------------------------------------------------------------------
__global__ void __launch_bounds__(128, 3) k_main(
        const int* __restrict__ path, const int* __restrict__ path_idx,
        const float* __restrict__ w_hh, const float* __restrict__ b_hh,
        const float* __restrict__ w_lin, const float* __restrict__ b_lin,
        float* __restrict__ out, int n_paths) {
    __shared__ ulonglong2 ws[GI_W * 8];
    __shared__ float bs[GI_W];
    __shared__ float wl[DD];
    __shared__ float bl;
    int tid = threadIdx.x;
    load_ws(ws, w_hh, tid, 128);
    if (tid < GI_W) bs[tid] = b_hh[tid];
    if (tid < DD) wl[tid] = tf32r(w_lin[tid]);
    if (tid == 0) bl = b_lin[0];
    __syncthreads();

    int p = blockIdx.x * 128 + tid;
    if (p >= n_paths) return;

    int b0 = __ldg(path + p * 5 + 0);
    int b1 = __ldg(path + p * 5 + 1);
    int b2 = __ldg(path + p * 5 + 2);
    int b3 = __ldg(path + p * 5 + 3);
    int b4 = __ldg(path + p * 5 + 4);

    u64 hu[16];
    const u64* h2 = (const u64*)(g_H2 + (b0 * NSYM + b1) * DD);
    #pragma unroll
    for (int q = 0; q < 16; q++) hu[q] = __ldg(h2 + q);

    const float* g2 = g_GI_ent + b2 * GI_W;
    const float* g3 = g_GI_rel + b3 * GI_W;
    const float* g4 = g_GI_ent + b4 * GI_W;
    #pragma unroll 1
    for (int t = 0; t < 3; t++) {
        const float* gi = (t == 0) ? g2 : (t == 1) ? g3 : g4;
        gru_step(hu, gi, ws, bs);
    }

    // per_path = h . w_lin + b_lin  (TF32 operands, fp32 acc, bias last;
    // s0 = first 16 dims, s1 = second 16 — same grouping as round 3)
    float s0 = 0.0f, s1 = 0.0f;
    #pragma unroll
    for (int pq = 0; pq < 8; pq++) {
        float a, b; unpack2(hu[pq], a, b);
        s0 = fmaf(tf32r(a), wl[2 * pq + 0], s0);
        s0 = fmaf(tf32r(b), wl[2 * pq + 1], s0);
        float c, d; unpack2(hu[8 + pq], c, d);
        s1 = fmaf(tf32r(c), wl[16 + 2 * pq + 0], s1);
        s1 = fmaf(tf32r(d), wl[16 + 2 * pq + 1], s1);
    }
    float s = (s0 + s1) + bl;

    atomicAdd(out + __ldg(path_idx + p), s);
}

// ---------------------------------------------------------------------------
extern "C" void kernel_launch(void* const* d_in, const int* in_sizes, int n_in,
                              void* d_out, int out_size) {
    // inputs: 0 users, 1 path, 2 path_idx, 3 all_emb, 4 edge_emb, 5 virtual_emb,
    //         6 w_ih, 7 w_hh, 8 b_ih, 9 b_hh, 10 w_lin, 11 b_lin
    const int*   path     = (const int*)d_in[1];
    const int*   path_idx = (const int*)d_in[2];
    const float* all_emb  = (const float*)d_in[3];
    const float* edge_emb = (const float*)d_in[4];
    const float* w_ih     = (const float*)d_in[6];
    const float* w_hh     = (const float*)d_in[7];
    const float* b_ih     = (const float*)d_in[8];
    const float* b_hh     = (const float*)d_in[9];
    const float* w_lin    = (const float*)d_in[10];
    const float* b_lin    = (const float*)d_in[11];
    float* out = (float*)d_out;
    int n_paths = in_sizes[2];

    k_zero<<<1, 1024>>>(out, out_size);
    k_gi<<<128, 96>>>(all_emb, edge_emb, w_ih, b_ih);
    k_h2<<<32, 128>>>(w_hh, b_hh);
    int grid = (n_paths + 127) / 128;
    k_main<<<grid, 128>>>(path, path_idx, w_hh, b_hh, w_lin, b_lin, out, n_paths);
}

// round 5
// speedup vs baseline: 1.2659x; 1.0050x over previous
#include <cuda_runtime.h>

#define DD 32          // embed dim
#define GI_W 96        // 3*DD gate width
#define NSYM 64        // distinct path symbol values

typedef unsigned long long u64;

// Precomputed tables (device globals: no dynamic allocation allowed)
__device__ float g_GI_ent[NSYM * GI_W];   // W_ih @ all_emb[e] + b_ih   (even positions)
__device__ float g_GI_rel[NSYM * GI_W];   // W_ih @ edge_emb[r] + b_ih  (odd positions)
__device__ float g_H2[NSYM * NSYM * DD];  // GRU state after 2 steps, keyed (p0, p1)

// ---------------------------------------------------------------------------
// TF32 emulation (the reference's matmuls are TF32 tensor-core GEMMs):
// round GEMM operands to TF32, accumulate fp32. tf32*tf32 is exact in fp32.
// ---------------------------------------------------------------------------
__device__ __forceinline__ float tf32r(float x) {
    float r;
    asm("cvt.rna.tf32.f32 %0, %1;" : "=f"(r) : "f"(x));
    return r;
}

// Packed f32x2 helpers (sm_100+; FFMA2 in SASS, only reachable via PTX)
__device__ __forceinline__ u64 pack2(float lo, float hi) {
    u64 r; asm("mov.b64 %0, {%1, %2};" : "=l"(r) : "f"(lo), "f"(hi)); return r;
}
__device__ __forceinline__ void unpack2(u64 v, float& lo, float& hi) {
    asm("mov.b64 {%0, %1}, %2;" : "=f"(lo), "=f"(hi) : "l"(v));
}
__device__ __forceinline__ u64 fma2(u64 a, u64 b, u64 c) {
    u64 d; asm("fma.rn.f32x2 %0, %1, %2, %3;" : "=l"(d) : "l"(a), "l"(b), "l"(c));
    return d;
}
__device__ __forceinline__ u64 mul2(u64 a, u64 b) {
    u64 d; asm("mul.rn.f32x2 %0, %1, %2;" : "=l"(d) : "l"(a), "l"(b));
    return d;
}

// Fast activations — proven in round 1 to contribute <=4e-8 to final rel_err
// (vs the 4.3e-4 TF32 floor).
__device__ __forceinline__ float sigf(float x) {
    return __fdividef(1.0f, 1.0f + __expf(-x));
}
__device__ __forceinline__ float tanh_fast(float x) {
    return fmaf(2.0f, sigf(2.0f * x), -1.0f);
}

// 32-wide dot of one TF32-rounded w_hh row (8 ulonglong2 in smem, broadcast
// LDS.128) against packed TF32-rounded h. Dual packed accumulators.
__device__ __forceinline__ float dot32(const ulonglong2* __restrict__ wrow,
                                       const u64 hr[16]) {
    u64 a0 = 0ull, a1 = 0ull;   // packed {0.f, 0.f}
    #pragma unroll
    for (int q = 0; q < 8; q++) {
        ulonglong2 w = wrow[q];
        a0 = fma2(w.x, hr[2 * q + 0], a0);
        a1 = fma2(w.y, hr[2 * q + 1], a1);
    }
    float x0, x1, y0, y1;
    unpack2(a0, x0, x1);
    unpack2(a1, y0, y1);
    return (x0 + y0) + (x1 + y1);
}

// ---------------------------------------------------------------------------
// One GRU step on packed state hu[16] ({h0,h1},{h2,h3},...).
// ws: 96 rows x 8 ulonglong2 of TF32-rounded w_hh. bs: b_hh (fp32).
// Chunk order r -> n -> z; rn[16] holds r then n (packed).
// ---------------------------------------------------------------------------
__device__ __forceinline__ void gru_step(u64 hu[16], const float* __restrict__ gi,
                                         const ulonglong2* __restrict__ ws,
                                         const float* __restrict__ bs) {
    // TF32-round the GEMM operand copy of h (state itself stays full fp32)
    u64 hr[16];
    #pragma unroll
    for (int p = 0; p < 16; p++) {
        float lo, hi; unpack2(hu[p], lo, hi);
        hr[p] = pack2(tf32r(lo), tf32r(hi));
    }

    u64 rn[16];
    const float4* gi4 = (const float4*)gi;
    float4 giv;

    // --- r chunk (rows 0..31) ---
    #pragma unroll
    for (int jp = 0; jp < 16; jp++) {
        if ((jp & 1) == 0) giv = __ldg(gi4 + (jp >> 1));
        float g0 = (jp & 1) ? giv.z : giv.x;
        float g1 = (jp & 1) ? giv.w : giv.y;
        float d0 = dot32(ws + (2 * jp + 0) * 8, hr);
        float d1 = dot32(ws + (2 * jp + 1) * 8, hr);
        float r0 = sigf(g0 + (d0 + bs[2 * jp + 0]));
        float r1 = sigf(g1 + (d1 + bs[2 * jp + 1]));
        rn[jp] = pack2(r0, r1);
    }

    // --- n chunk (rows 64..95): n = tanh(gi_n + r * gh_n) ---
    #pragma unroll
    for (int jp = 0; jp < 16; jp++) {
        if ((jp & 1) == 0) giv = __ldg(gi4 + 16 + (jp >> 1));
        float g0 = (jp & 1) ? giv.z : giv.x;
        float g1 = (jp & 1) ? giv.w : giv.y;
        float d0 = dot32(ws + (64 + 2 * jp + 0) * 8, hr);
        float d1 = dot32(ws + (64 + 2 * jp + 1) * 8, hr);
        float r0, r1; unpack2(rn[jp], r0, r1);
        float n0 = tanh_fast(fmaf(r0, d0 + bs[64 + 2 * jp + 0], g0));
        float n1 = tanh_fast(fmaf(r1, d1 + bs[64 + 2 * jp + 1], g1));
        rn[jp] = pack2(n0, n1);
    }

    // --- z chunk (rows 32..63) + packed update: h = z*h + (1-z)*n ---
    #pragma unroll
    for (int jp = 0; jp < 16; jp++) {
        if ((jp & 1) == 0) giv = __ldg(gi4 + 8 + (jp >> 1));
        float g0 = (jp & 1) ? giv.z : giv.x;
        float g1 = (jp & 1) ? giv.w : giv.y;
        float d0 = dot32(ws + (32 + 2 * jp + 0) * 8, hr);
        float d1 = dot32(ws + (32 + 2 * jp + 1) * 8, hr);
        float z0 = sigf(g0 + (d0 + bs[32 + 2 * jp + 0]));
        float z1 = sigf(g1 + (d1 + bs[32 + 2 * jp + 1]));
        u64 zz  = pack2(z0, z1);
        u64 omz = pack2(1.0f - z0, 1.0f - z1);
        hu[jp] = fma2(zz, hu[jp], mul2(omz, rn[jp]));
    }
}

// Shared loader: w_hh -> TF32-rounded packed rows in smem
__device__ __forceinline__ void load_ws(ulonglong2* ws, const float* __restrict__ w_hh,
                                        int tid, int nthreads) {
    for (int i = tid; i < GI_W * 8; i += nthreads) {
        float4 v = ((const float4*)w_hh)[i];
        ulonglong2 e;
        e.x = pack2(tf32r(v.x), tf32r(v.y));
        e.y = pack2(tf32r(v.z), tf32r(v.w));
        ws[i] = e;
    }
}

// ---------------------------------------------------------------------------
// K0: zero the (poisoned) output
// ---------------------------------------------------------------------------
__global__ void k_zero(float* out, int n) {
    int i = threadIdx.x;
    if (i < n) out[i] = 0.0f;
}

// ---------------------------------------------------------------------------
// K1: GI tables — TF32 products (matching the reference einsum), fp64 sum.
// ---------------------------------------------------------------------------
__global__ void k_gi(const float* __restrict__ all_emb,
                     const float* __restrict__ edge_emb,
                     const float* __restrict__ w_ih,
                     const float* __restrict__ b_ih) {
    int row = blockIdx.x;      // 0..127
    int j = threadIdx.x;       // 0..95
    const float* x = (row < NSYM) ? (all_emb + row * DD)
                                  : (edge_emb + (row - NSYM) * DD);
    const float* w = w_ih + j * DD;
    double acc = 0.0;
    #pragma unroll
    for (int k = 0; k < DD; k++) {
        float wt = tf32r(__ldg(w + k));
        float xt = tf32r(__ldg(x + k));
        acc += (double)wt * (double)xt;     // tf32*tf32 exact
    }
    acc += (double)__ldg(b_ih + j);
    float* dst = (row < NSYM) ? (g_GI_ent + row * GI_W)
                              : (g_GI_rel + (row - NSYM) * GI_W);
    dst[j] = (float)acc;
}

// ---------------------------------------------------------------------------
// K2: H2 table. One thread per (p0, p1) key: steps 1 and 2 of the GRU.
// ---------------------------------------------------------------------------
__global__ void __launch_bounds__(128, 3) k_h2(const float* __restrict__ w_hh,
                                               const float* __restrict__ b_hh) {
    __shared__ ulonglong2 ws[GI_W * 8];
    __shared__ float bs[GI_W];
    int tid = threadIdx.x;
    load_ws(ws, w_hh, tid, 128);
    if (tid < GI_W) bs[tid] = b_hh[tid];
    __syncthreads();

    int key = blockIdx.x * 128 + tid;        // 0..4095
    int e0 = key >> 6, r1 = key & 63;

    // step 1: h0 = 0 => gh = b_hh exactly (TF32 GEMM of zeros is zero)
    const float* gi = g_GI_ent + e0 * GI_W;
    u64 hu[16];
    #pragma unroll
    for (int jp = 0; jp < 16; jp++) {
        float hv[2];
        #pragma unroll
        for (int t = 0; t < 2; t++) {
            int j = 2 * jp + t;
            float r = sigf(__ldg(gi + j) + bs[j]);
            float z = sigf(__ldg(gi + 32 + j) + bs[32 + j]);
            float n = tanh_fast(fmaf(r, bs[64 + j], __ldg(gi + 64 + j)));
            hv[t] = (1.0f - z) * n;          // + z*0
        }
        hu[jp] = pack2(hv[0], hv[1]);
    }
    // step 2
    gru_step(hu, g_GI_rel + r1 * GI_W, ws, bs);

    u64* dst = (u64*)(g_H2 + key * DD);
    #pragma unroll
    for (int p = 0; p < 16; p++) dst[p] = hu[p];
}

// ---------------------------------------------------------------------------
// K3: main per-path kernel. One thread per path: load h2, 3 GRU steps,
//     linear head, atomic segment sum.
// ---------------------------------------------------------------------------
__global__ void __launch_bounds__(128, 3) k_main(
        const int* __restrict__ path, const int* __restrict__ path_idx,
        const float* __restrict__ w_hh, const float* __restrict__ b_hh,
        const float* __restrict__ w_lin, const float* __restrict__ b_lin,
        float* __restrict__ out, int n_paths) {
    __shared__ ulonglong2 ws[GI_W * 8];
    __shared__ float bs[GI_W];
    __shared__ float wl[DD];
    __shared__ float bl;
    int tid = threadIdx.x;
    load_ws(ws, w_hh, tid, 128);
    if (tid < GI_W) bs[tid] = b_hh[tid];
    if (tid < DD) wl[tid] = tf32r(w_lin[tid]);
    if (tid == 0) bl = b_lin[0];
    __syncthreads();

    int p = blockIdx.x * 128 + tid;
    if (p >= n_paths) return;

    int b0 = __ldg(path + p * 5 + 0);
    int b1 = __ldg(path + p * 5 + 1);
    int b2 = __ldg(path + p * 5 + 2);
    int b3 = __ldg(path + p * 5 + 3);
    int b4 = __ldg(path + p * 5 + 4);

    u64 hu[16];
    const u64* h2 = (const u64*)(g_H2 + (b0 * NSYM + b1) * DD);
    #pragma unroll
    for (int q = 0; q < 16; q++) hu[q] = __ldg(h2 + q);

    const float* g2 = g_GI_ent + b2 * GI_W;
    const float* g3 = g_GI_rel + b3 * GI_W;
    const float* g4 = g_GI_ent + b4 * GI_W;
    #pragma unroll 1
    for (int t = 0; t < 3; t++) {
        const float* gi = (t == 0) ? g2 : (t == 1) ? g3 : g4;
        gru_step(hu, gi, ws, bs);
    }

    // per_path = h . w_lin + b_lin  (TF32 operands, fp32 acc, bias last;
    // s0 = first 16 dims, s1 = second 16 — same grouping as round 3)
    float s0 = 0.0f, s1 = 0.0f;
    #pragma unroll
    for (int pq = 0; pq < 8; pq++) {
        float a, b; unpack2(hu[pq], a, b);
        s0 = fmaf(tf32r(a), wl[2 * pq + 0], s0);
        s0 = fmaf(tf32r(b), wl[2 * pq + 1], s0);
        float c, d; unpack2(hu[8 + pq], c, d);
        s1 = fmaf(tf32r(c), wl[16 + 2 * pq + 0], s1);
        s1 = fmaf(tf32r(d), wl[16 + 2 * pq + 1], s1);
    }
    float s = (s0 + s1) + bl;

    atomicAdd(out + __ldg(path_idx + p), s);
}

// ---------------------------------------------------------------------------
extern "C" void kernel_launch(void* const* d_in, const int* in_sizes, int n_in,
                              void* d_out, int out_size) {
    // inputs: 0 users, 1 path, 2 path_idx, 3 all_emb, 4 edge_emb, 5 virtual_emb,
    //         6 w_ih, 7 w_hh, 8 b_ih, 9 b_hh, 10 w_lin, 11 b_lin
    const int*   path     = (const int*)d_in[1];
    const int*   path_idx = (const int*)d_in[2];
    const float* all_emb  = (const float*)d_in[3];
    const float* edge_emb = (const float*)d_in[4];
    const float* w_ih     = (const float*)d_in[6];
    const float* w_hh     = (const float*)d_in[7];
    const float* b_ih     = (const float*)d_in[8];
    const float* b_hh     = (const float*)d_in[9];
    const float* w_lin    = (const float*)d_in[10];
    const float* b_lin    = (const float*)d_in[11];
    float* out = (float*)d_out;
    int n_paths = in_sizes[2];

    k_zero<<<1, 1024>>>(out, out_size);
    k_gi<<<128, 96>>>(all_emb, edge_emb, w_ih, b_ih);
    k_h2<<<32, 128>>>(w_hh, b_hh);
    int grid = (n_paths + 127) / 128;
    k_main<<<grid, 128>>>(path, path_idx, w_hh, b_hh, w_lin, b_lin, out, n_paths);
}

// round 6
// speedup vs baseline: 3.5255x; 2.7848x over previous
#include <cuda_runtime.h>
#include <cstdint>

#define DD 32          // embed dim
#define GI_W 96        // 3*DD gate width
#define NSYM 64        // distinct path symbol values

typedef unsigned long long u64;
typedef uint32_t u32;

// ---------------------------------------------------------------------------
// Precomputed tables (device globals: no dynamic allocation allowed)
// ---------------------------------------------------------------------------
__device__ float g_GI_ent[NSYM * GI_W];    // W_ih @ all_emb[e] + b_ih (for H2 build)
__device__ float g_GI_rel[NSYM * GI_W];
__device__ float g_H2[NSYM * NSYM * DD];   // GRU state after 2 steps, key (b0,b1)
__device__ float2 g_XT[2][NSYM][16];       // tf32-rounded embeddings, A-frag gather
                                           // layout: [tab][sym][kt*4+m] = {x[8kt+m], x[8kt+m+4]}
__device__ float4 g_Bfrag[2][12][2][32];   // MMA B fragments [0]=W_hh,[1]=W_ih
                                           // [mat][nt][kp][lane] = {kt=2kp:b0,b1, kt=2kp+1:b0,b1}
__device__ float  g_bias[128];             // [0..63]=b_ih+b_hh (r,z) [64..95]=b_ih(n) [96..127]=b_hh(n)
__device__ float  g_wlr[DD];               // tf32-rounded w_lin

// ---------------------------------------------------------------------------
// TF32 emulation (reference matmuls are TF32 tensor-core GEMMs)
// ---------------------------------------------------------------------------
__device__ __forceinline__ float tf32r(float x) {
    float r;
    asm("cvt.rna.tf32.f32 %0, %1;" : "=f"(r) : "f"(x));
    return r;
}

// Packed f32x2 helpers (used by scalar H2 build)
__device__ __forceinline__ u64 pack2(float lo, float hi) {
    u64 r; asm("mov.b64 %0, {%1, %2};" : "=l"(r) : "f"(lo), "f"(hi)); return r;
}
__device__ __forceinline__ void unpack2(u64 v, float& lo, float& hi) {
    asm("mov.b64 {%0, %1}, %2;" : "=f"(lo), "=f"(hi) : "l"(v));
}
__device__ __forceinline__ u64 fma2(u64 a, u64 b, u64 c) {
    u64 d; asm("fma.rn.f32x2 %0, %1, %2, %3;" : "=l"(d) : "l"(a), "l"(b), "l"(c));
    return d;
}
__device__ __forceinline__ u64 mul2(u64 a, u64 b) {
    u64 d; asm("mul.rn.f32x2 %0, %1, %2;" : "=l"(d) : "l"(a), "l"(b));
    return d;
}

// Fast activations — proven (round 1 vs 2) to contribute <=4e-8 to final rel_err
__device__ __forceinline__ float sigf(float x) {
    return __fdividef(1.0f, 1.0f + __expf(-x));
}
__device__ __forceinline__ float tanh_fast(float x) {
    return fmaf(2.0f, sigf(2.0f * x), -1.0f);
}

// tf32 MMA: D(16x8) += A(16x8) * B(8x8), fp32 accumulate
__device__ __forceinline__ void mma8(float c[4], const u32 a[4], u32 b0, u32 b1) {
    asm volatile(
        "mma.sync.aligned.m16n8k8.row.col.f32.tf32.tf32.f32 "
        "{%0,%1,%2,%3}, {%4,%5,%6,%7}, {%8,%9}, {%0,%1,%2,%3};"
        : "+f"(c[0]), "+f"(c[1]), "+f"(c[2]), "+f"(c[3])
        : "r"(a[0]), "r"(a[1]), "r"(a[2]), "r"(a[3]), "r"(b0), "r"(b1));
}

// ---------------------------------------------------------------------------
// Scalar 32-wide dot + GRU step (used only by the tiny H2-build kernel)
// ---------------------------------------------------------------------------
__device__ __forceinline__ float dot32(const ulonglong2* __restrict__ wrow,
                                       const u64 hr[16]) {
    u64 a0 = 0ull, a1 = 0ull;
    #pragma unroll
    for (int q = 0; q < 8; q++) {
        ulonglong2 w = wrow[q];
        a0 = fma2(w.x, hr[2 * q + 0], a0);
        a1 = fma2(w.y, hr[2 * q + 1], a1);
    }
    float x0, x1, y0, y1;
    unpack2(a0, x0, x1);
    unpack2(a1, y0, y1);
    return (x0 + y0) + (x1 + y1);
}

__device__ __forceinline__ void gru_step_scalar(u64 hu[16], const float* __restrict__ gi,
                                                const ulonglong2* __restrict__ ws,
                                                const float* __restrict__ bs) {
    u64 hr[16];
    #pragma unroll
    for (int p = 0; p < 16; p++) {
        float lo, hi; unpack2(hu[p], lo, hi);
        hr[p] = pack2(tf32r(lo), tf32r(hi));
    }
    u64 rn[16];
    const float4* gi4 = (const float4*)gi;
    float4 giv;
    #pragma unroll
    for (int jp = 0; jp < 16; jp++) {
        if ((jp & 1) == 0) giv = __ldg(gi4 + (jp >> 1));
        float g0 = (jp & 1) ? giv.z : giv.x;
        float g1 = (jp & 1) ? giv.w : giv.y;
        float d0 = dot32(ws + (2 * jp + 0) * 8, hr);
        float d1 = dot32(ws + (2 * jp + 1) * 8, hr);
        rn[jp] = pack2(sigf(g0 + (d0 + bs[2 * jp + 0])),
                       sigf(g1 + (d1 + bs[2 * jp + 1])));
    }
    #pragma unroll
    for (int jp = 0; jp < 16; jp++) {
        if ((jp & 1) == 0) giv = __ldg(gi4 + 16 + (jp >> 1));
        float g0 = (jp & 1) ? giv.z : giv.x;
        float g1 = (jp & 1) ? giv.w : giv.y;
        float d0 = dot32(ws + (64 + 2 * jp + 0) * 8, hr);
        float d1 = dot32(ws + (64 + 2 * jp + 1) * 8, hr);
        float r0, r1; unpack2(rn[jp], r0, r1);
        rn[jp] = pack2(tanh_fast(fmaf(r0, d0 + bs[64 + 2 * jp + 0], g0)),
                       tanh_fast(fmaf(r1, d1 + bs[64 + 2 * jp + 1], g1)));
    }
    #pragma unroll
    for (int jp = 0; jp < 16; jp++) {
        if ((jp & 1) == 0) giv = __ldg(gi4 + 8 + (jp >> 1));
        float g0 = (jp & 1) ? giv.z : giv.x;
        float g1 = (jp & 1) ? giv.w : giv.y;
        float d0 = dot32(ws + (32 + 2 * jp + 0) * 8, hr);
        float d1 = dot32(ws + (32 + 2 * jp + 1) * 8, hr);
        float z0 = sigf(g0 + (d0 + bs[32 + 2 * jp + 0]));
        float z1 = sigf(g1 + (d1 + bs[32 + 2 * jp + 1]));
        hu[jp] = fma2(pack2(z0, z1), hu[jp],
                      mul2(pack2(1.0f - z0, 1.0f - z1), rn[jp]));
    }
}

// ---------------------------------------------------------------------------
// K0: zero the (poisoned) output
// ---------------------------------------------------------------------------
__global__ void k_zero(float* out, int n) {
    int i = threadIdx.x;
    if (i < n) out[i] = 0.0f;
}

// ---------------------------------------------------------------------------
// K1: GI tables (TF32 products, fp64 sum) — used by the H2 build
// ---------------------------------------------------------------------------
__global__ void k_gi(const float* __restrict__ all_emb,
                     const float* __restrict__ edge_emb,
                     const float* __restrict__ w_ih,
                     const float* __restrict__ b_ih) {
    int row = blockIdx.x;      // 0..127
    int j = threadIdx.x;       // 0..95
    const float* x = (row < NSYM) ? (all_emb + row * DD)
                                  : (edge_emb + (row - NSYM) * DD);
    const float* w = w_ih + j * DD;
    double acc = 0.0;
    #pragma unroll
    for (int k = 0; k < DD; k++)
        acc += (double)tf32r(__ldg(w + k)) * (double)tf32r(__ldg(x + k));
    acc += (double)__ldg(b_ih + j);
    float* dst = (row < NSYM) ? (g_GI_ent + row * GI_W)
                              : (g_GI_rel + (row - NSYM) * GI_W);
    dst[j] = (float)acc;
}

// ---------------------------------------------------------------------------
// K_prep: MMA-side tables — X fragments, B fragments, biases, rounded w_lin
// ---------------------------------------------------------------------------
__global__ void k_prep(const float* __restrict__ all_emb,
                       const float* __restrict__ edge_emb,
                       const float* __restrict__ w_ih,
                       const float* __restrict__ w_hh,
                       const float* __restrict__ b_ih,
                       const float* __restrict__ b_hh,
                       const float* __restrict__ w_lin) {
    int i = blockIdx.x * blockDim.x + threadIdx.x;
    // XT: 2 tables * 64 syms * 16 float2
    if (i < 2048) {
        int tab = i >> 10, rem = i & 1023;
        int sym = rem >> 4, idx = rem & 15;
        int kt = idx >> 2, m = idx & 3;
        const float* src = tab ? (edge_emb + sym * DD) : (all_emb + sym * DD);
        g_XT[tab][sym][idx] = make_float2(tf32r(src[8 * kt + m]),
                                          tf32r(src[8 * kt + m + 4]));
    }
    // B fragments: 2 mats * 12 nt * 2 kp * 32 lanes
    int j = i - 4096;
    if (j >= 0 && j < 1536) {
        int lane = j & 31;
        int r1 = j >> 5;          // 0..47
        int kp = r1 & 1;
        int r2 = r1 >> 1;         // 0..23
        int nt = r2 % 12, mat = r2 / 12;
        const float* W = mat ? w_ih : w_hh;
        int row = 8 * nt + (lane >> 2);
        int k0 = 16 * kp + (lane & 3);
        g_Bfrag[mat][nt][kp][lane] = make_float4(
            tf32r(W[row * DD + k0]),     tf32r(W[row * DD + k0 + 4]),
            tf32r(W[row * DD + k0 + 8]), tf32r(W[row * DD + k0 + 12]));
    }
    // biases
    int k = i - 8192;
    if (k >= 0 && k < 128) {
        float v;
        if (k < 64)      v = b_ih[k] + b_hh[k];   // r,z fused bias
        else if (k < 96) v = b_ih[k];             // n gates: input bias (gate = k)
        else             v = b_hh[k - 32];        // n gates: hidden bias
        g_bias[k] = v;
    }
    int w = i - 8448;
    if (w >= 0 && w < DD) g_wlr[w] = tf32r(w_lin[w]);
}

// ---------------------------------------------------------------------------
// K2: H2 table (scalar path, 4096 threads — negligible time)
// ---------------------------------------------------------------------------
__global__ void __launch_bounds__(128, 3) k_h2(const float* __restrict__ w_hh,
                                               const float* __restrict__ b_hh) {
    __shared__ ulonglong2 ws[GI_W * 8];
    __shared__ float bs[GI_W];
    int tid = threadIdx.x;
    for (int i = tid; i < GI_W * 8; i += 128) {
        float4 v = ((const float4*)w_hh)[i];
        ulonglong2 e;
        e.x = pack2(tf32r(v.x), tf32r(v.y));
        e.y = pack2(tf32r(v.z), tf32r(v.w));
        ws[i] = e;
    }
    if (tid < GI_W) bs[tid] = b_hh[tid];
    __syncthreads();

    int key = blockIdx.x * 128 + tid;
    int e0 = key >> 6, r1 = key & 63;

    const float* gi = g_GI_ent + e0 * GI_W;
    u64 hu[16];
    #pragma unroll
    for (int jp = 0; jp < 16; jp++) {
        float hv[2];
        #pragma unroll
        for (int t = 0; t < 2; t++) {
            int j = 2 * jp + t;
            float r = sigf(__ldg(gi + j) + bs[j]);
            float z = sigf(__ldg(gi + 32 + j) + bs[32 + j]);
            float n = tanh_fast(fmaf(r, bs[64 + j], __ldg(gi + 64 + j)));
            hv[t] = (1.0f - z) * n;
        }
        hu[jp] = pack2(hv[0], hv[1]);
    }
    gru_step_scalar(hu, g_GI_rel + r1 * GI_W, ws, bs);

    u64* dst = (u64*)(g_H2 + key * DD);
    #pragma unroll
    for (int p = 0; p < 16; p++) dst[p] = hu[p];
}

// ---------------------------------------------------------------------------
// K3: main kernel, tensor-core version. One warp = 16 paths (one m16 tile).
// State H (16x32) lives in mma C-fragment registers; per step:
//   GH(16x96) = [H|X](16x64) @ [W_hh|W_ih]^T   via m16n8k8 tf32 MMA
// r,z gates: fused h+x accumulation; n gates: separate (r scales only h-part).
// ---------------------------------------------------------------------------
__global__ void __launch_bounds__(128, 3) k_main(
        const int* __restrict__ path, const int* __restrict__ path_idx,
        const float* __restrict__ b_lin, float* __restrict__ out, int n_paths) {
    __shared__ float4 sB[2][12][2][32];
    __shared__ float sBias[128];
    __shared__ float sWl[DD];

    int tid = threadIdx.x;
    {
        const float4* src = &g_Bfrag[0][0][0][0];
        float4* dst = &sB[0][0][0][0];
        for (int i = tid; i < 1536; i += 128) dst[i] = src[i];
        sBias[tid] = g_bias[tid];
        if (tid < DD) sWl[tid] = g_wlr[tid];
    }
    __syncthreads();

    int warp = tid >> 5, lane = tid & 31;
    int m = lane & 3, grp = lane >> 2;
    int s0 = 4 * grp + (m >> 1), s1 = s0 + 2;   // src lanes for C->A relayout
    bool esel = (m & 1) != 0;

    int pbase = (blockIdx.x * 4 + warp) * 16;
    int p0 = pbase + grp;        // fragment row grp
    int p1 = p0 + 8;             // fragment row grp+8
    int n1 = n_paths - 1;
    int pc0 = min(p0, n1), pc1 = min(p1, n1);

    const int* P0 = path + pc0 * 5;
    const int* P1 = path + pc1 * 5;
    int b00 = __ldg(P0 + 0), b01 = __ldg(P0 + 1), b02 = __ldg(P0 + 2),
        b03 = __ldg(P0 + 3), b04 = __ldg(P0 + 4);
    int b10 = __ldg(P1 + 0), b11 = __ldg(P1 + 1), b12 = __ldg(P1 + 2),
        b13 = __ldg(P1 + 3), b14 = __ldg(P1 + 4);

    // Load H2 state directly into C-fragment layout:
    // c0:(grp, 2m+8nt) c1:(grp, 2m+1+8nt) c2:(grp+8, ...) c3
    float h_c[4][4];
    const float* H0 = g_H2 + (b00 * NSYM + b01) * DD;
    const float* H1 = g_H2 + (b10 * NSYM + b11) * DD;
    #pragma unroll
    for (int nt = 0; nt < 4; nt++) {
        float2 v0 = *(const float2*)(H0 + 8 * nt + 2 * m);
        float2 v1 = *(const float2*)(H1 + 8 * nt + 2 * m);
        h_c[nt][0] = v0.x; h_c[nt][1] = v0.y;
        h_c[nt][2] = v1.x; h_c[nt][3] = v1.y;
    }

    float rn[4][4];   // r, then n (reused in place)

    #pragma unroll 1
    for (int t = 0; t < 3; t++) {
        const float2* xt;
        int sym0, sym1;
        if (t == 0)      { xt = &g_XT[0][0][0]; sym0 = b02; sym1 = b12; }
        else if (t == 1) { xt = &g_XT[1][0][0]; sym0 = b03; sym1 = b13; }
        else             { xt = &g_XT[0][0][0]; sym0 = b04; sym1 = b14; }

        // Build A fragments: a0:(grp,c) a1:(grp+8,c) a2:(grp,c+4) a3:(grp+8,c+4)
        u32 Ah[4][4], Ax[4][4];
        #pragma unroll
        for (int kt = 0; kt < 4; kt++) {
            float v0 = __shfl_sync(0xffffffffu, h_c[kt][0], s0);
            float v1 = __shfl_sync(0xffffffffu, h_c[kt][1], s0);
            float v2 = __shfl_sync(0xffffffffu, h_c[kt][2], s0);
            float v3 = __shfl_sync(0xffffffffu, h_c[kt][3], s0);
            float w0 = __shfl_sync(0xffffffffu, h_c[kt][0], s1);
            float w1 = __shfl_sync(0xffffffffu, h_c[kt][1], s1);
            float w2 = __shfl_sync(0xffffffffu, h_c[kt][2], s1);
            float w3 = __shfl_sync(0xffffffffu, h_c[kt][3], s1);
            Ah[kt][0] = __float_as_uint(tf32r(esel ? v1 : v0));
            Ah[kt][1] = __float_as_uint(tf32r(esel ? v3 : v2));
            Ah[kt][2] = __float_as_uint(tf32r(esel ? w1 : w0));
            Ah[kt][3] = __float_as_uint(tf32r(esel ? w3 : w2));
            float2 q0 = __ldg(xt + sym0 * 16 + kt * 4 + m);
            float2 q1 = __ldg(xt + sym1 * 16 + kt * 4 + m);
            Ax[kt][0] = __float_as_uint(q0.x);
            Ax[kt][1] = __float_as_uint(q1.x);
            Ax[kt][2] = __float_as_uint(q0.y);
            Ax[kt][3] = __float_as_uint(q1.y);
        }

        // fused h+x GEMM for an 8-gate block nt (r and z gates)
        auto gemm_rz = [&](int nt, float c[4]) {
            c[0] = c[1] = c[2] = c[3] = 0.0f;
            #pragma unroll
            for (int kp = 0; kp < 2; kp++) {
                float4 bh = sB[0][nt][kp][lane];
                mma8(c, Ah[2 * kp + 0], __float_as_uint(bh.x), __float_as_uint(bh.y));
                mma8(c, Ah[2 * kp + 1], __float_as_uint(bh.z), __float_as_uint(bh.w));
                float4 bi = sB[1][nt][kp][lane];
                mma8(c, Ax[2 * kp + 0], __float_as_uint(bi.x), __float_as_uint(bi.y));
                mma8(c, Ax[2 * kp + 1], __float_as_uint(bi.z), __float_as_uint(bi.w));
            }
        };

        // --- r gates (0..31, B nt 0..3) ---
        #pragma unroll
        for (int nt = 0; nt < 4; nt++) {
            float c[4]; gemm_rz(nt, c);
            float2 bb = *(const float2*)&sBias[8 * nt + 2 * m];
            rn[nt][0] = sigf(c[0] + bb.x);
            rn[nt][1] = sigf(c[1] + bb.y);
            rn[nt][2] = sigf(c[2] + bb.x);
            rn[nt][3] = sigf(c[3] + bb.y);
        }

        // --- n gates (64..95, B nt 8..11): n = tanh(i_n + r*h_n), separate GEMMs ---
        #pragma unroll
        for (int nt = 0; nt < 4; nt++) {
            float ch[4] = {0, 0, 0, 0}, ci[4] = {0, 0, 0, 0};
            #pragma unroll
            for (int kp = 0; kp < 2; kp++) {
                float4 bh = sB[0][8 + nt][kp][lane];
                mma8(ch, Ah[2 * kp + 0], __float_as_uint(bh.x), __float_as_uint(bh.y));
                mma8(ch, Ah[2 * kp + 1], __float_as_uint(bh.z), __float_as_uint(bh.w));
                float4 bi = sB[1][8 + nt][kp][lane];
                mma8(ci, Ax[2 * kp + 0], __float_as_uint(bi.x), __float_as_uint(bi.y));
                mma8(ci, Ax[2 * kp + 1], __float_as_uint(bi.z), __float_as_uint(bi.w));
            }
            float2 bi2 = *(const float2*)&sBias[64 + 8 * nt + 2 * m];
            float2 bh2 = *(const float2*)&sBias[96 + 8 * nt + 2 * m];
            rn[nt][0] = tanh_fast(fmaf(rn[nt][0], ch[0] + bh2.x, ci[0] + bi2.x));
            rn[nt][1] = tanh_fast(fmaf(rn[nt][1], ch[1] + bh2.y, ci[1] + bi2.y));
            rn[nt][2] = tanh_fast(fmaf(rn[nt][2], ch[2] + bh2.x, ci[2] + bi2.x));
            rn[nt][3] = tanh_fast(fmaf(rn[nt][3], ch[3] + bh2.y, ci[3] + bi2.y));
        }

        // --- z gates (32..63, B nt 4..7) + state update h = z*h + (1-z)*n ---
        #pragma unroll
        for (int nt = 0; nt < 4; nt++) {
            float c[4]; gemm_rz(4 + nt, c);
            float2 bb = *(const float2*)&sBias[32 + 8 * nt + 2 * m];
            float z0 = sigf(c[0] + bb.x);
            float z1 = sigf(c[1] + bb.y);
            float z2 = sigf(c[2] + bb.x);
            float z3 = sigf(c[3] + bb.y);
            h_c[nt][0] = fmaf(z0, h_c[nt][0], (1.0f - z0) * rn[nt][0]);
            h_c[nt][1] = fmaf(z1, h_c[nt][1], (1.0f - z1) * rn[nt][1]);
            h_c[nt][2] = fmaf(z2, h_c[nt][2], (1.0f - z2) * rn[nt][2]);
            h_c[nt][3] = fmaf(z3, h_c[nt][3], (1.0f - z3) * rn[nt][3]);
        }
    }

    // Head: s = tf32(h) . tf32(w_lin) + b_lin, quad-reduced (lanes of a quad
    // hold disjoint column pairs of the same two paths)
    float sc0 = 0.0f, sc1 = 0.0f;
    #pragma unroll
    for (int nt = 0; nt < 4; nt++) {
        float2 wl = *(const float2*)&sWl[8 * nt + 2 * m];
        sc0 = fmaf(tf32r(h_c[nt][0]), wl.x, sc0);
        sc0 = fmaf(tf32r(h_c[nt][1]), wl.y, sc0);
        sc1 = fmaf(tf32r(h_c[nt][2]), wl.x, sc1);
        sc1 = fmaf(tf32r(h_c[nt][3]), wl.y, sc1);
    }
    sc0 += __shfl_xor_sync(0xffffffffu, sc0, 1);
    sc0 += __shfl_xor_sync(0xffffffffu, sc0, 2);
    sc1 += __shfl_xor_sync(0xffffffffu, sc1, 1);
    sc1 += __shfl_xor_sync(0xffffffffu, sc1, 2);

    float bl = __ldg(b_lin);
    if (m == 0) {
        if (p0 < n_paths) atomicAdd(out + __ldg(path_idx + p0), sc0 + bl);
        if (p1 < n_paths) atomicAdd(out + __ldg(path_idx + p1), sc1 + bl);
    }
}

// ---------------------------------------------------------------------------
extern "C" void kernel_launch(void* const* d_in, const int* in_sizes, int n_in,
                              void* d_out, int out_size) {
    // inputs: 0 users, 1 path, 2 path_idx, 3 all_emb, 4 edge_emb, 5 virtual_emb,
    //         6 w_ih, 7 w_hh, 8 b_ih, 9 b_hh, 10 w_lin, 11 b_lin
    const int*   path     = (const int*)d_in[1];
    const int*   path_idx = (const int*)d_in[2];
    const float* all_emb  = (const float*)d_in[3];
    const float* edge_emb = (const float*)d_in[4];
    const float* w_ih     = (const float*)d_in[6];
    const float* w_hh     = (const float*)d_in[7];
    const float* b_ih     = (const float*)d_in[8];
    const float* b_hh     = (const float*)d_in[9];
    const float* w_lin    = (const float*)d_in[10];
    const float* b_lin    = (const float*)d_in[11];
    float* out = (float*)d_out;
    int n_paths = in_sizes[2];

    k_zero<<<1, 1024>>>(out, out_size);
    k_gi<<<128, 96>>>(all_emb, edge_emb, w_ih, b_ih);
    k_prep<<<34, 256>>>(all_emb, edge_emb, w_ih, w_hh, b_ih, b_hh, w_lin);
    k_h2<<<32, 128>>>(w_hh, b_hh);
    int nblocks = (n_paths + 63) / 64;   // 64 paths per block (4 warps x 16)
    k_main<<<nblocks, 128>>>(path, path_idx, b_lin, out, n_paths);
}

// round 7
// speedup vs baseline: 4.1552x; 1.1786x over previous
#include <cuda_runtime.h>
#include <cstdint>

#define DD 32          // embed dim
#define GI_W 96        // 3*DD gate width
#define NSYM 64        // distinct path symbol values

typedef uint32_t u32;

// ---------------------------------------------------------------------------
// Precomputed tables (device globals: no dynamic allocation allowed)
// ---------------------------------------------------------------------------
__device__ float g_GI_ent[NSYM * GI_W];    // W_ih @ all_emb[e] + b_ih (for H1 build)
__device__ float g_H1[NSYM * DD];          // GRU state after step 1 (key b0)
__device__ float g_H2[NSYM * NSYM * DD];   // GRU state after 2 steps, key (b0,b1)
__device__ float2 g_XT[2][NSYM][16];       // tf32-rounded embeddings, A-frag gather
                                           // [tab][sym][kt*4+m] = {x[8kt+m], x[8kt+m+4]}
__device__ float4 g_Bfrag[2][12][2][32];   // MMA B fragments [0]=W_hh,[1]=W_ih
__device__ float  g_bias[128];             // [0..63]=b_ih+b_hh (r,z) [64..95]=b_ih(n) [96..127]=b_hh(n)
__device__ float  g_wlr[DD];               // tf32-rounded w_lin

// ---------------------------------------------------------------------------
// TF32 emulation (reference matmuls are TF32 tensor-core GEMMs)
// ---------------------------------------------------------------------------
__device__ __forceinline__ float tf32r(float x) {
    float r;
    asm("cvt.rna.tf32.f32 %0, %1;" : "=f"(r) : "f"(x));
    return r;
}

// MUFU-native activations. tanh.approx abs err ~1e-5 — negligible against the
// 4.3e-4 TF32 floor (round-1/2 evidence: activation precision moved rel_err 4e-8).
__device__ __forceinline__ float tanh_mufu(float x) {
    float r;
    asm("tanh.approx.f32 %0, %1;" : "=f"(r) : "f"(x));
    return r;
}
__device__ __forceinline__ float sig_mufu(float x) {
    return fmaf(0.5f, tanh_mufu(0.5f * x), 0.5f);
}

// tf32 MMA: D(16x8) += A(16x8) * B(8x8), fp32 accumulate
__device__ __forceinline__ void mma8(float c[4], const u32 a[4], u32 b0, u32 b1) {
    asm volatile(
        "mma.sync.aligned.m16n8k8.row.col.f32.tf32.tf32.f32 "
        "{%0,%1,%2,%3}, {%4,%5,%6,%7}, {%8,%9}, {%0,%1,%2,%3};"
        : "+f"(c[0]), "+f"(c[1]), "+f"(c[2]), "+f"(c[3])
        : "r"(a[0]), "r"(a[1]), "r"(a[2]), "r"(a[3]), "r"(b0), "r"(b1));
}

// ---------------------------------------------------------------------------
// One MMA GRU step on C-fragment state h_c[4][4] (16 paths per warp).
//   GH(16x96) = [H|X](16x64) @ [W_hh|W_ih]^T  via m16n8k8 tf32 MMA
// r,z gates: fused h+x accumulation (fused bias); n gates: separate (r scales
// only the hidden part). X A-fragments gathered from g_XT by symbol.
// ---------------------------------------------------------------------------
__device__ __forceinline__ void gru_step_mma(
        float h_c[4][4], const float2* __restrict__ xt, int sym0, int sym1,
        const float4 (*sB)[12][2][32], const float* __restrict__ sBias,
        int lane, int m, int s0, int s1, bool esel) {
    // Build A fragments: a0:(grp,c) a1:(grp+8,c) a2:(grp,c+4) a3:(grp+8,c+4)
    u32 Ah[4][4], Ax[4][4];
    #pragma unroll
    for (int kt = 0; kt < 4; kt++) {
        float v0 = __shfl_sync(0xffffffffu, h_c[kt][0], s0);
        float v1 = __shfl_sync(0xffffffffu, h_c[kt][1], s0);
        float v2 = __shfl_sync(0xffffffffu, h_c[kt][2], s0);
        float v3 = __shfl_sync(0xffffffffu, h_c[kt][3], s0);
        float w0 = __shfl_sync(0xffffffffu, h_c[kt][0], s1);
        float w1 = __shfl_sync(0xffffffffu, h_c[kt][1], s1);
        float w2 = __shfl_sync(0xffffffffu, h_c[kt][2], s1);
        float w3 = __shfl_sync(0xffffffffu, h_c[kt][3], s1);
        Ah[kt][0] = __float_as_uint(tf32r(esel ? v1 : v0));
        Ah[kt][1] = __float_as_uint(tf32r(esel ? v3 : v2));
        Ah[kt][2] = __float_as_uint(tf32r(esel ? w1 : w0));
        Ah[kt][3] = __float_as_uint(tf32r(esel ? w3 : w2));
        float2 q0 = __ldg(xt + sym0 * 16 + kt * 4 + m);
        float2 q1 = __ldg(xt + sym1 * 16 + kt * 4 + m);
        Ax[kt][0] = __float_as_uint(q0.x);
        Ax[kt][1] = __float_as_uint(q1.x);
        Ax[kt][2] = __float_as_uint(q0.y);
        Ax[kt][3] = __float_as_uint(q1.y);
    }

    float rn[4][4];

    auto gemm_rz = [&](int nt, float c[4]) {
        c[0] = c[1] = c[2] = c[3] = 0.0f;
        #pragma unroll
        for (int kp = 0; kp < 2; kp++) {
            float4 bh = sB[0][nt][kp][lane];
            mma8(c, Ah[2 * kp + 0], __float_as_uint(bh.x), __float_as_uint(bh.y));
            mma8(c, Ah[2 * kp + 1], __float_as_uint(bh.z), __float_as_uint(bh.w));
            float4 bi = sB[1][nt][kp][lane];
            mma8(c, Ax[2 * kp + 0], __float_as_uint(bi.x), __float_as_uint(bi.y));
            mma8(c, Ax[2 * kp + 1], __float_as_uint(bi.z), __float_as_uint(bi.w));
        }
    };

    // --- r gates (0..31, B nt 0..3) ---
    #pragma unroll
    for (int nt = 0; nt < 4; nt++) {
        float c[4]; gemm_rz(nt, c);
        float2 bb = *(const float2*)&sBias[8 * nt + 2 * m];
        rn[nt][0] = sig_mufu(c[0] + bb.x);
        rn[nt][1] = sig_mufu(c[1] + bb.y);
        rn[nt][2] = sig_mufu(c[2] + bb.x);
        rn[nt][3] = sig_mufu(c[3] + bb.y);
    }

    // --- n gates (64..95, B nt 8..11): n = tanh(i_n + r*h_n), separate GEMMs ---
    #pragma unroll
    for (int nt = 0; nt < 4; nt++) {
        float ch[4] = {0, 0, 0, 0}, ci[4] = {0, 0, 0, 0};
        #pragma unroll
        for (int kp = 0; kp < 2; kp++) {
            float4 bh = sB[0][8 + nt][kp][lane];
            mma8(ch, Ah[2 * kp + 0], __float_as_uint(bh.x), __float_as_uint(bh.y));
            mma8(ch, Ah[2 * kp + 1], __float_as_uint(bh.z), __float_as_uint(bh.w));
            float4 bi = sB[1][8 + nt][kp][lane];
            mma8(ci, Ax[2 * kp + 0], __float_as_uint(bi.x), __float_as_uint(bi.y));
            mma8(ci, Ax[2 * kp + 1], __float_as_uint(bi.z), __float_as_uint(bi.w));
        }
        float2 bi2 = *(const float2*)&sBias[64 + 8 * nt + 2 * m];
        float2 bh2 = *(const float2*)&sBias[96 + 8 * nt + 2 * m];
        rn[nt][0] = tanh_mufu(fmaf(rn[nt][0], ch[0] + bh2.x, ci[0] + bi2.x));
        rn[nt][1] = tanh_mufu(fmaf(rn[nt][1], ch[1] + bh2.y, ci[1] + bi2.y));
        rn[nt][2] = tanh_mufu(fmaf(rn[nt][2], ch[2] + bh2.x, ci[2] + bi2.x));
        rn[nt][3] = tanh_mufu(fmaf(rn[nt][3], ch[3] + bh2.y, ci[3] + bi2.y));
    }

    // --- z gates (32..63, B nt 4..7) + state update h = z*h + (1-z)*n ---
    #pragma unroll
    for (int nt = 0; nt < 4; nt++) {
        float c[4]; gemm_rz(4 + nt, c);
        float2 bb = *(const float2*)&sBias[32 + 8 * nt + 2 * m];
        float z0 = sig_mufu(c[0] + bb.x);
        float z1 = sig_mufu(c[1] + bb.y);
        float z2 = sig_mufu(c[2] + bb.x);
        float z3 = sig_mufu(c[3] + bb.y);
        h_c[nt][0] = fmaf(z0, h_c[nt][0], (1.0f - z0) * rn[nt][0]);
        h_c[nt][1] = fmaf(z1, h_c[nt][1], (1.0f - z1) * rn[nt][1]);
        h_c[nt][2] = fmaf(z2, h_c[nt][2], (1.0f - z2) * rn[nt][2]);
        h_c[nt][3] = fmaf(z3, h_c[nt][3], (1.0f - z3) * rn[nt][3]);
    }
}

// ---------------------------------------------------------------------------
// K_setup: fused zero + GI(ent) + XT/Bfrag/bias/w_lin prep. One launch.
// thread segments: [0,1024) zero | [1024,7168) GI ent | [7168,9216) XT
//                  [9216,10752) Bfrag | [10752,10880) bias | [10880,10912) wl
// ---------------------------------------------------------------------------
__global__ void k_setup(float* out, int out_size,
                        const float* __restrict__ all_emb,
                        const float* __restrict__ edge_emb,
                        const float* __restrict__ w_ih,
                        const float* __restrict__ w_hh,
                        const float* __restrict__ b_ih,
                        const float* __restrict__ b_hh,
                        const float* __restrict__ w_lin) {
    int i = blockIdx.x * blockDim.x + threadIdx.x;
    if (i < 1024) {
        for (int k = i; k < out_size; k += 1024) out[k] = 0.0f;
        return;
    }
    int gi = i - 1024;
    if (gi < 6144) {               // GI ent: TF32 products, fp64 sum
        int row = gi / GI_W, j = gi % GI_W;
        const float* x = all_emb + row * DD;
        const float* w = w_ih + j * DD;
        double acc = 0.0;
        #pragma unroll
        for (int k = 0; k < DD; k++)
            acc += (double)tf32r(__ldg(w + k)) * (double)tf32r(__ldg(x + k));
        acc += (double)__ldg(b_ih + j);
        g_GI_ent[row * GI_W + j] = (float)acc;
        return;
    }
    int xi = i - 7168;
    if (xi >= 0 && xi < 2048) {    // XT fragments
        int tab = xi >> 10, rem = xi & 1023;
        int sym = rem >> 4, idx = rem & 15;
        int kt = idx >> 2, m = idx & 3;
        const float* src = tab ? (edge_emb + sym * DD) : (all_emb + sym * DD);
        g_XT[tab][sym][idx] = make_float2(tf32r(src[8 * kt + m]),
                                          tf32r(src[8 * kt + m + 4]));
        return;
    }
    int j = i - 9216;
    if (j >= 0 && j < 1536) {      // B fragments
        int lane = j & 31;
        int r1 = j >> 5;
        int kp = r1 & 1;
        int r2 = r1 >> 1;
        int nt = r2 % 12, mat = r2 / 12;
        const float* W = mat ? w_ih : w_hh;
        int row = 8 * nt + (lane >> 2);
        int k0 = 16 * kp + (lane & 3);
        g_Bfrag[mat][nt][kp][lane] = make_float4(
            tf32r(W[row * DD + k0]),     tf32r(W[row * DD + k0 + 4]),
            tf32r(W[row * DD + k0 + 8]), tf32r(W[row * DD + k0 + 12]));
        return;
    }
    int k = i - 10752;
    if (k >= 0 && k < 128) {       // biases
        float v;
        if (k < 64)      v = b_ih[k] + b_hh[k];
        else if (k < 96) v = b_ih[k];
        else             v = b_hh[k - 32];
        g_bias[k] = v;
        return;
    }
    int w = i - 10880;
    if (w >= 0 && w < DD) g_wlr[w] = tf32r(w_lin[w]);
}

// ---------------------------------------------------------------------------
// K_h1: step 1 from h0=0 — depends only on b0 (64 keys x 32 dims, elementwise)
// ---------------------------------------------------------------------------
__global__ void k_h1(const float* __restrict__ b_hh) {
    int i = blockIdx.x * blockDim.x + threadIdx.x;
    if (i >= NSYM * DD) return;
    int e0 = i >> 5, j = i & 31;
    const float* gi = g_GI_ent + e0 * GI_W;
    float r = sig_mufu(gi[j] + __ldg(b_hh + j));
    float z = sig_mufu(gi[32 + j] + __ldg(b_hh + 32 + j));
    float n = tanh_mufu(fmaf(r, __ldg(b_hh + 64 + j), gi[64 + j]));
    g_H1[e0 * DD + j] = (1.0f - z) * n;
}

// ---------------------------------------------------------------------------
// K_h2: H2 table via MMA. One warp = 16 consecutive keys; one GRU step
// from h1[key>>6] with x = edge_emb[key & 63].
// ---------------------------------------------------------------------------
__global__ void __launch_bounds__(128) k_h2(int dummy) {
    __shared__ float4 sB[2][12][2][32];
    __shared__ float sBias[128];
    int tid = threadIdx.x;
    {
        const float4* src = &g_Bfrag[0][0][0][0];
        float4* dst = &sB[0][0][0][0];
        for (int i = tid; i < 1536; i += 128) dst[i] = src[i];
        sBias[tid] = g_bias[tid];
    }
    __syncthreads();

    int warp = tid >> 5, lane = tid & 31;
    int m = lane & 3, grp = lane >> 2;
    int s0 = 4 * grp + (m >> 1), s1 = s0 + 2;
    bool esel = (m & 1) != 0;

    int kbase = (blockIdx.x * 4 + warp) * 16;
    int key0 = kbase + grp;        // fragment row grp
    int key1 = key0 + 8;           // fragment row grp+8
    int e00 = key0 >> 6, r10 = key0 & 63;
    int e01 = key1 >> 6, r11 = key1 & 63;

    // Load h1 into C-fragment layout
    float h_c[4][4];
    const float* H0 = g_H1 + e00 * DD;
    const float* H1 = g_H1 + e01 * DD;
    #pragma unroll
    for (int nt = 0; nt < 4; nt++) {
        float2 v0 = *(const float2*)(H0 + 8 * nt + 2 * m);
        float2 v1 = *(const float2*)(H1 + 8 * nt + 2 * m);
        h_c[nt][0] = v0.x; h_c[nt][1] = v0.y;
        h_c[nt][2] = v1.x; h_c[nt][3] = v1.y;
    }

    gru_step_mma(h_c, &g_XT[1][0][0], r10, r11, sB, sBias, lane, m, s0, s1, esel);

    // Store to g_H2 row-major (same layout k_main loads)
    float* D0 = g_H2 + key0 * DD;
    float* D1 = g_H2 + key1 * DD;
    #pragma unroll
    for (int nt = 0; nt < 4; nt++) {
        *(float2*)(D0 + 8 * nt + 2 * m) = make_float2(h_c[nt][0], h_c[nt][1]);
        *(float2*)(D1 + 8 * nt + 2 * m) = make_float2(h_c[nt][2], h_c[nt][3]);
    }
}

// ---------------------------------------------------------------------------
// K_main: one warp = 16 paths; load H2, 3 MMA GRU steps, head, atomic sum.
// ---------------------------------------------------------------------------
__global__ void __launch_bounds__(128, 3) k_main(
        const int* __restrict__ path, const int* __restrict__ path_idx,
        const float* __restrict__ b_lin, float* __restrict__ out, int n_paths) {
    __shared__ float4 sB[2][12][2][32];
    __shared__ float sBias[128];
    __shared__ float sWl[DD];

    int tid = threadIdx.x;
    {
        const float4* src = &g_Bfrag[0][0][0][0];
        float4* dst = &sB[0][0][0][0];
        for (int i = tid; i < 1536; i += 128) dst[i] = src[i];
        sBias[tid] = g_bias[tid];
        if (tid < DD) sWl[tid] = g_wlr[tid];
    }
    __syncthreads();

    int warp = tid >> 5, lane = tid & 31;
    int m = lane & 3, grp = lane >> 2;
    int s0 = 4 * grp + (m >> 1), s1 = s0 + 2;
    bool esel = (m & 1) != 0;

    int pbase = (blockIdx.x * 4 + warp) * 16;
    int p0 = pbase + grp;
    int p1 = p0 + 8;
    int n1 = n_paths - 1;
    int pc0 = min(p0, n1), pc1 = min(p1, n1);

    const int* P0 = path + pc0 * 5;
    const int* P1 = path + pc1 * 5;
    int b00 = __ldg(P0 + 0), b01 = __ldg(P0 + 1), b02 = __ldg(P0 + 2),
        b03 = __ldg(P0 + 3), b04 = __ldg(P0 + 4);
    int b10 = __ldg(P1 + 0), b11 = __ldg(P1 + 1), b12 = __ldg(P1 + 2),
        b13 = __ldg(P1 + 3), b14 = __ldg(P1 + 4);

    // Load H2 state into C-fragment layout
    float h_c[4][4];
    const float* H0 = g_H2 + (b00 * NSYM + b01) * DD;
    const float* H1 = g_H2 + (b10 * NSYM + b11) * DD;
    #pragma unroll
    for (int nt = 0; nt < 4; nt++) {
        float2 v0 = *(const float2*)(H0 + 8 * nt + 2 * m);
        float2 v1 = *(const float2*)(H1 + 8 * nt + 2 * m);
        h_c[nt][0] = v0.x; h_c[nt][1] = v0.y;
        h_c[nt][2] = v1.x; h_c[nt][3] = v1.y;
    }

    #pragma unroll 1
    for (int t = 0; t < 3; t++) {
        const float2* xt;
        int sym0, sym1;
        if (t == 0)      { xt = &g_XT[0][0][0]; sym0 = b02; sym1 = b12; }
        else if (t == 1) { xt = &g_XT[1][0][0]; sym0 = b03; sym1 = b13; }
        else             { xt = &g_XT[0][0][0]; sym0 = b04; sym1 = b14; }
        gru_step_mma(h_c, xt, sym0, sym1, sB, sBias, lane, m, s0, s1, esel);
    }

    // Head: s = tf32(h) . tf32(w_lin) + b_lin, quad-reduced
    float sc0 = 0.0f, sc1 = 0.0f;
    #pragma unroll
    for (int nt = 0; nt < 4; nt++) {
        float2 wl = *(const float2*)&sWl[8 * nt + 2 * m];
        sc0 = fmaf(tf32r(h_c[nt][0]), wl.x, sc0);
        sc0 = fmaf(tf32r(h_c[nt][1]), wl.y, sc0);
        sc1 = fmaf(tf32r(h_c[nt][2]), wl.x, sc1);
        sc1 = fmaf(tf32r(h_c[nt][3]), wl.y, sc1);
    }
    sc0 += __shfl_xor_sync(0xffffffffu, sc0, 1);
    sc0 += __shfl_xor_sync(0xffffffffu, sc0, 2);
    sc1 += __shfl_xor_sync(0xffffffffu, sc1, 1);
    sc1 += __shfl_xor_sync(0xffffffffu, sc1, 2);

    float bl = __ldg(b_lin);
    if (m == 0) {
        if (p0 < n_paths) atomicAdd(out + __ldg(path_idx + p0), sc0 + bl);
        if (p1 < n_paths) atomicAdd(out + __ldg(path_idx + p1), sc1 + bl);
    }
}

// ---------------------------------------------------------------------------
extern "C" void kernel_launch(void* const* d_in, const int* in_sizes, int n_in,
                              void* d_out, int out_size) {
    // inputs: 0 users, 1 path, 2 path_idx, 3 all_emb, 4 edge_emb, 5 virtual_emb,
    //         6 w_ih, 7 w_hh, 8 b_ih, 9 b_hh, 10 w_lin, 11 b_lin
    const int*   path     = (const int*)d_in[1];
    const int*   path_idx = (const int*)d_in[2];
    const float* all_emb  = (const float*)d_in[3];
    const float* edge_emb = (const float*)d_in[4];
    const float* w_ih     = (const float*)d_in[6];
    const float* w_hh     = (const float*)d_in[7];
    const float* b_ih     = (const float*)d_in[8];
    const float* b_hh     = (const float*)d_in[9];
    const float* w_lin    = (const float*)d_in[10];
    const float* b_lin    = (const float*)d_in[11];
    float* out = (float*)d_out;
    int n_paths = in_sizes[2];

    k_setup<<<43, 256>>>(out, out_size, all_emb, edge_emb, w_ih, w_hh,
                         b_ih, b_hh, w_lin);
    k_h1<<<2, 1024>>>(b_hh);
    k_h2<<<64, 128>>>(0);
    int nblocks = (n_paths + 63) / 64;   // 64 paths per block (4 warps x 16)
    k_main<<<nblocks, 128>>>(path, path_idx, b_lin, out, n_paths);
}